// round 14
// baseline (speedup 1.0000x reference)
#include <cuda_runtime.h>
#include <cuda_bf16.h>
#include <math.h>
#include <stdint.h>

#define NN 100000
#define EE 1600000
#define IN_CH 64
#define HH 128
#define H3 384
#define GG 4096
#define FULL 0xffffffffu
#define BG_SMEM 49152   // 3 stages x 4096 words

// ---------------- scratch (no allocations allowed) ----------------
__device__ float d_x0[NN * HH];
__device__ float d_xw[NN * HH];
__device__ float d_xc[NN * HH];
__device__ float d_gi[NN * H3];     // grz (NN x 256)
__device__ float d_gh[NN * H3];     // gih (NN x 256)
__device__ float d_asrc[NN];
__device__ float d_adst[NN];
__device__ float d_outG[GG * HH];
__device__ float d_giG[GG * H3];
__device__ float d_ghG[GG * H3];
__device__ float d_vvec[HH];
__device__ int d_deg[NN];
__device__ int d_ptr[NN + 1];
__device__ int d_cur[NN];
__device__ int d_csr_src[EE];
__device__ int d_bsum[128];
__device__ int d_gptr[GG + 1];
// combined split activation buffers: row = 256 words = [h split | x split]
__device__ uint32_t s_hx[NN * 256];
__device__ uint32_t s_hxG[GG * 256];
__device__ uint32_t s_x[NN * IN_CH];
// split weights
__device__ uint32_t w_lin1[HH * IN_CH];
__device__ uint32_t w_g1[HH * HH];
__device__ uint32_t w_g2[HH * HH];
__device__ uint32_t w_atom[2 * HH * HH];
__device__ uint32_t w_mol[HH * HH];
__device__ uint32_t w_rz0[256 * 256];
__device__ uint32_t w_rza[2 * 256 * 256];
__device__ uint32_t w_rzm[256 * 256];
__device__ uint32_t w_in0[HH * HH];
__device__ uint32_t w_hn0[HH * HH];
__device__ uint32_t w_ina[2 * HH * HH];
__device__ uint32_t w_hna[2 * HH * HH];
__device__ uint32_t w_inm[HH * HH];
__device__ uint32_t w_hnm[HH * HH];
__device__ float b_rz0[256];
__device__ float b_rza[2 * 256];
__device__ float b_rzm[256];

// ---------------- helpers ----------------
__device__ __forceinline__ float warp_sum_all(float v) {
#pragma unroll
    for (int o = 16; o > 0; o >>= 1) v += __shfl_xor_sync(FULL, v, o);
    return v;
}
__device__ __forceinline__ float warp_max_all(float v) {
#pragma unroll
    for (int o = 16; o > 0; o >>= 1) v = fmaxf(v, __shfl_xor_sync(FULL, v, o));
    return v;
}

__device__ __forceinline__ int ilv(int cp) {
    int c = cp >> 3, p = cp & 7;
    return (c << 4) + ((p < 4) ? (p << 2) : (((p - 4) << 2) + 1));
}

__device__ __forceinline__ void split_pair(float f0, float f1, uint32_t& hp, uint32_t& lp) {
    uint32_t u0 = __float_as_uint(f0), u1 = __float_as_uint(f1);
    hp = __byte_perm(u0, u1, 0x7632);
    float l0 = f0 - __uint_as_float(u0 & 0xffff0000u);
    float l1 = f1 - __uint_as_float(u1 & 0xffff0000u);
    __nv_bfloat162 p = __floats2bfloat162_rn(l0, l1);
    lp = *reinterpret_cast<uint32_t*>(&p);
}

__device__ __forceinline__ void mma_bf16(float* c, const uint32_t* a, const uint32_t* b) {
    asm volatile(
        "mma.sync.aligned.m16n8k16.row.col.f32.bf16.bf16.f32 "
        "{%0,%1,%2,%3}, {%4,%5,%6,%7}, {%8,%9}, {%0,%1,%2,%3};"
        : "+f"(c[0]), "+f"(c[1]), "+f"(c[2]), "+f"(c[3])
        : "r"(a[0]), "r"(a[1]), "r"(a[2]), "r"(a[3]), "r"(b[0]), "r"(b[1]));
}

__device__ __forceinline__ void cp_async16(uint32_t dst, const void* src, bool pred) {
    asm volatile("cp.async.cg.shared.global [%0], [%1], 16, %2;"
                 :: "r"(dst), "l"(src), "r"(pred ? 16 : 0));
}

// ---------------- batched weight split ----------------
struct SDesc { const float* src; uint32_t* dst; int ld, M, K; };
struct SDescs { SDesc d[14]; };

__global__ void to_split_batch(SDescs ds) {
    SDesc d = ds.d[blockIdx.x];
    int kh = d.K >> 1;
    int total = d.M * kh;
    for (int idx = blockIdx.y * 256 + threadIdx.x; idx < total; idx += gridDim.y * 256) {
        int r = idx / kh, j = idx - r * kh;
        float f0 = d.src[(size_t)r * d.ld + 2 * j];
        float f1 = d.src[(size_t)r * d.ld + 2 * j + 1];
        uint32_t hp, lp;
        split_pair(f0, f1, hp, lp);
        int w = ilv(j);
        d.dst[(size_t)r * d.K + w] = hp;
        d.dst[(size_t)r * d.K + w + 2] = lp;
    }
}

struct CDesc { const float* wi; const float* wh; uint32_t* dst; const float* bi; const float* bh; float* brz; };
struct CDescs { CDesc d[4]; };

__global__ void concat_rz_batch(CDescs ds) {
    CDesc d = ds.d[blockIdx.x];
    for (int idx = blockIdx.y * 256 + threadIdx.x; idx < 256 * 128; idx += gridDim.y * 256) {
        int n = idx >> 7, j = idx & 127;
        float f0, f1;
        if (j < 64) {
            f0 = d.wi[(size_t)n * HH + 2 * j];
            f1 = d.wi[(size_t)n * HH + 2 * j + 1];
        } else {
            f0 = d.wh[(size_t)n * HH + 2 * (j - 64)];
            f1 = d.wh[(size_t)n * HH + 2 * (j - 64) + 1];
        }
        uint32_t hp, lp;
        split_pair(f0, f1, hp, lp);
        int w = ilv(j);
        d.dst[(size_t)n * 256 + w] = hp;
        d.dst[(size_t)n * 256 + w + 2] = lp;
        if (j == 0) d.brz[n] = d.bi[n] + d.bh[n];
    }
}

__global__ void to_split_x(const float* __restrict__ src, uint32_t* __restrict__ dst) {
    int idx = blockIdx.x * blockDim.x + threadIdx.x;
    if (idx >= NN * 32) return;
    int r = idx >> 5, j = idx & 31;
    float f0 = src[(size_t)r * IN_CH + 2 * j];
    float f1 = src[(size_t)r * IN_CH + 2 * j + 1];
    uint32_t hp, lp;
    split_pair(f0, f1, hp, lp);
    int w = ilv(j);
    dst[(size_t)r * IN_CH + w] = hp;
    dst[(size_t)r * IN_CH + w + 2] = lp;
}

// ---------------- bf16-split tensor-core GEMM: multi-job + fused attention dots ----
// Dotted jobs require their full N=128 in ONE block tile (ctile covers all cols):
// row-dot finished in-block via quad-shuffle + smem, plain store (no atomics).
struct GJob {
    const uint32_t* B;
    const float* bias;
    float* C;                 // optional (null = no dense write)
    uint32_t* Cs;             // optional split write
    const float* av;  float* aout;   // optional: aout[row] = dot(u, av), u = act'(v)
    const float* av2; float* aout2;  // optional second dot (uses raw v)
    const float* ab;                  // optional per-col bias for u (strided)
    int abstride, aact;               // aact=1: u = lrelu(v + ab[c*abstride])
    int aoff, K, ldc, coff, csld, csoff, act;
};
struct GLaunch {
    GJob j[3];
    int jid[4];
    int ctile[4];
};

__device__ __forceinline__ void bload(const uint32_t* __restrict__ Ahl, int lda, int aoff,
                                      const uint32_t* __restrict__ Bhl, int K,
                                      int M, int row0, int col0,
                                      int tid, int kc, uint32_t* sb) {
#pragma unroll
    for (int it = 0; it < 8; it++) {
        int s = tid * 8 + it;
        int r = (s >> 2) & 127;
        int j = s & 3;
        bool isB = s >= 512;
        uint32_t da = (uint32_t)__cvta_generic_to_shared(sb + (isB ? 2048 : 0) + r * 16 + 4 * j);
        const uint32_t* g;
        bool pred = true;
        if (!isB) {
            int ar = row0 + r;
            pred = ar < M;
            g = Ahl + (size_t)(pred ? ar : 0) * lda + aoff + kc * 16 + 4 * j;
        } else {
            g = Bhl + (size_t)(col0 + r) * K + kc * 16 + 4 * j;
        }
        cp_async16(da, g, pred);
    }
    asm volatile("cp.async.commit_group;");
}

__global__ void __launch_bounds__(128) bgemm(GLaunch L, const uint32_t* __restrict__ Ahl,
                                             int lda, int M) {
    extern __shared__ uint32_t sm[];
    const GJob J = L.j[L.jid[blockIdx.x]];
    const int col0 = L.ctile[blockIdx.x] * 128;
    const int tid = threadIdx.x;
    const int lane = tid & 31;
    const int warp = tid >> 5;
    const int g = lane >> 2;
    const int t = lane & 3;
    const int wrow = (warp >> 1) * 64;
    const int wcol = (warp & 1) * 64;
    const int row0 = blockIdx.y * 128;
    const int nk = J.K >> 4;

    float acc[4][8][4];
#pragma unroll
    for (int mt = 0; mt < 4; mt++)
#pragma unroll
        for (int nt = 0; nt < 8; nt++)
#pragma unroll
            for (int i = 0; i < 4; i++) acc[mt][nt][i] = 0.f;

    bload(Ahl, lda, J.aoff, J.B, J.K, M, row0, col0, tid, 0, sm);
    bload(Ahl, lda, J.aoff, J.B, J.K, M, row0, col0, tid, 1, sm + 4096);

    for (int c = 0; c < nk; c++) {
        if (c + 1 < nk)
            asm volatile("cp.async.wait_group 1;");
        else
            asm volatile("cp.async.wait_group 0;");
        __syncthreads();
        if (c + 2 < nk) {
            int nb = c + 2; nb -= (nb / 3) * 3;
            bload(Ahl, lda, J.aoff, J.B, J.K, M, row0, col0, tid, c + 2, sm + nb * 4096);
        }
        int cb = c; cb -= (cb / 3) * 3;
        const uint32_t* As = sm + cb * 4096;
        const uint32_t* Bs = As + 2048;

        uint32_t bhi[8][2], blo[8][2];
#pragma unroll
        for (int nt = 0; nt < 8; nt++) {
            int cc = wcol + nt * 8 + g;
            uint4 bb = *(const uint4*)(Bs + cc * 16 + 4 * t);
            bhi[nt][0] = bb.x; bhi[nt][1] = bb.y;
            blo[nt][0] = bb.z; blo[nt][1] = bb.w;
        }
#pragma unroll
        for (int mt = 0; mt < 4; mt++) {
            int r = wrow + mt * 16 + g;
            uint4 a0 = *(const uint4*)(As + r * 16 + 4 * t);
            uint4 a8 = *(const uint4*)(As + (r + 8) * 16 + 4 * t);
            uint32_t ahi[4] = {a0.x, a8.x, a0.y, a8.y};
            uint32_t alo[4] = {a0.z, a8.z, a0.w, a8.w};
#pragma unroll
            for (int nt = 0; nt < 8; nt++) {
                mma_bf16(acc[mt][nt], alo, bhi[nt]);
                mma_bf16(acc[mt][nt], ahi, blo[nt]);
                mma_bf16(acc[mt][nt], ahi, bhi[nt]);
            }
        }
    }

    float ad1[4][2] = {};
    float ad2[4][2] = {};
#pragma unroll
    for (int mt = 0; mt < 4; mt++) {
#pragma unroll
        for (int nt = 0; nt < 8; nt++) {
            int r0 = row0 + wrow + mt * 16 + g;
            int cl = wcol + nt * 8 + 2 * t;
            int cg = col0 + cl;
            float b0 = J.bias ? J.bias[cg] : 0.f;
            float b1 = J.bias ? J.bias[cg + 1] : 0.f;
            float v00 = acc[mt][nt][0] + b0, v01 = acc[mt][nt][1] + b1;
            float v10 = acc[mt][nt][2] + b0, v11 = acc[mt][nt][3] + b1;
            if (J.act == 1) {
                v00 = v00 > 0.f ? v00 : 0.01f * v00;
                v01 = v01 > 0.f ? v01 : 0.01f * v01;
                v10 = v10 > 0.f ? v10 : 0.01f * v10;
                v11 = v11 > 0.f ? v11 : 0.01f * v11;
            }
            if (J.C) {
                if (r0 < M) {
                    J.C[(size_t)r0 * J.ldc + J.coff + cg] = v00;
                    J.C[(size_t)r0 * J.ldc + J.coff + cg + 1] = v01;
                    if (J.Cs) {
                        uint32_t hp, lp;
                        split_pair(v00, v01, hp, lp);
                        int w = J.csoff + ilv(cl >> 1);
                        J.Cs[(size_t)r0 * J.csld + w] = hp;
                        J.Cs[(size_t)r0 * J.csld + w + 2] = lp;
                    }
                }
                if (r0 + 8 < M) {
                    J.C[(size_t)(r0 + 8) * J.ldc + J.coff + cg] = v10;
                    J.C[(size_t)(r0 + 8) * J.ldc + J.coff + cg + 1] = v11;
                    if (J.Cs) {
                        uint32_t hp, lp;
                        split_pair(v10, v11, hp, lp);
                        int w = J.csoff + ilv(cl >> 1);
                        J.Cs[(size_t)(r0 + 8) * J.csld + w] = hp;
                        J.Cs[(size_t)(r0 + 8) * J.csld + w + 2] = lp;
                    }
                }
            }
            if (J.av) {
                float u00 = v00, u01 = v01, u10 = v10, u11 = v11;
                if (J.aact) {
                    float e0 = J.ab[(size_t)cg * J.abstride];
                    float e1 = J.ab[(size_t)(cg + 1) * J.abstride];
                    u00 = v00 + e0; u00 = u00 > 0.f ? u00 : 0.01f * u00;
                    u01 = v01 + e1; u01 = u01 > 0.f ? u01 : 0.01f * u01;
                    u10 = v10 + e0; u10 = u10 > 0.f ? u10 : 0.01f * u10;
                    u11 = v11 + e1; u11 = u11 > 0.f ? u11 : 0.01f * u11;
                }
                float a0 = J.av[cg], a1 = J.av[cg + 1];
                ad1[mt][0] += u00 * a0 + u01 * a1;
                ad1[mt][1] += u10 * a0 + u11 * a1;
                if (J.av2) {
                    float c0 = J.av2[cg], c1 = J.av2[cg + 1];
                    ad2[mt][0] += v00 * c0 + v01 * c1;
                    ad2[mt][1] += v10 * c0 + v11 * c1;
                }
            }
        }
    }
    if (J.av) {
        // quad reduction across t (lanes g*4 + t): full row-dot within this warp's 64 cols
#pragma unroll
        for (int mt = 0; mt < 4; mt++)
#pragma unroll
            for (int i = 0; i < 2; i++) {
                ad1[mt][i] += __shfl_xor_sync(FULL, ad1[mt][i], 1);
                ad1[mt][i] += __shfl_xor_sync(FULL, ad1[mt][i], 2);
                ad2[mt][i] += __shfl_xor_sync(FULL, ad2[mt][i], 1);
                ad2[mt][i] += __shfl_xor_sync(FULL, ad2[mt][i], 2);
            }
        float* sd = (float*)sm;   // reuse pipeline smem (256 floats)
        __syncthreads();
        if ((warp & 1) && t == 0) {
#pragma unroll
            for (int mt = 0; mt < 4; mt++)
#pragma unroll
                for (int i = 0; i < 2; i++) {
                    int lr = wrow + mt * 16 + g + i * 8;
                    sd[lr] = ad1[mt][i];
                    sd[128 + lr] = ad2[mt][i];
                }
        }
        __syncthreads();
        if (!(warp & 1) && t == 0) {
#pragma unroll
            for (int mt = 0; mt < 4; mt++)
#pragma unroll
                for (int i = 0; i < 2; i++) {
                    int lr = wrow + mt * 16 + g + i * 8;
                    int r0 = row0 + lr;
                    if (r0 < M) {
                        J.aout[r0] = ad1[mt][i] + sd[lr];
                        if (J.av2) J.aout2[r0] = ad2[mt][i] + sd[128 + lr];
                    }
                }
        }
    }
}

// ---------------- CSR build ----------------
__global__ void hist_kernel(const int* __restrict__ dst, int* __restrict__ deg, int n_e) {
    int e = blockIdx.x * blockDim.x + threadIdx.x;
    if (e < n_e) atomicAdd(&deg[dst[e]], 1);
}

__global__ void scan_block(const int* __restrict__ in, int* __restrict__ out,
                           int* __restrict__ bsum, int n) {
    __shared__ int s[256];
    int t = threadIdx.x;
    int base = blockIdx.x * 1024 + t * 4;
    int v[4];
#pragma unroll
    for (int j = 0; j < 4; j++) v[j] = (base + j < n) ? in[base + j] : 0;
    int tsum = v[0] + v[1] + v[2] + v[3];
    s[t] = tsum;
    __syncthreads();
    for (int off = 1; off < 256; off <<= 1) {
        int x = (t >= off) ? s[t - off] : 0;
        __syncthreads();
        s[t] += x;
        __syncthreads();
    }
    int exc = s[t] - tsum;
    if (t == 255) bsum[blockIdx.x] = s[t];
    int run = exc;
#pragma unroll
    for (int j = 0; j < 4; j++) {
        if (base + j < n) out[base + j] = run;
        run += v[j];
    }
}

__global__ void scan_bsum(int* __restrict__ bsum, int nb) {
    __shared__ int s[128];
    int t = threadIdx.x;
    int orig = (t < nb) ? bsum[t] : 0;
    s[t] = orig;
    __syncthreads();
    for (int off = 1; off < 128; off <<= 1) {
        int x = (t >= off) ? s[t - off] : 0;
        __syncthreads();
        s[t] += x;
        __syncthreads();
    }
    if (t < nb) bsum[t] = s[t] - orig;
}

__global__ void scan_fixup(int* __restrict__ ptr, const int* __restrict__ bsum,
                           int* __restrict__ cur, int n, int total) {
    int i = blockIdx.x * blockDim.x + threadIdx.x;
    if (i < n) {
        int p = ptr[i] + bsum[i >> 10];
        ptr[i] = p;
        cur[i] = p;
    }
    if (i == 0) ptr[n] = total;
}

__global__ void scatter_csr(const int* __restrict__ src, const int* __restrict__ dst,
                            int* __restrict__ cur, int* __restrict__ csr_src, int n_e) {
    int e = blockIdx.x * blockDim.x + threadIdx.x;
    if (e >= n_e) return;
    int p = atomicAdd(&cur[dst[e]], 1);
    csr_src[p] = src[e];
}

__global__ void build_gptr(const int* __restrict__ batch, int* __restrict__ gptr, int n) {
    int i = blockIdx.x * blockDim.x + threadIdx.x;
    if (i >= n) return;
    int b = batch[i];
    int prev = (i == 0) ? -1 : batch[i - 1];
    for (int g = prev + 1; g <= b; g++) gptr[g] = i;
    if (i == n - 1)
        for (int g = b + 1; g <= GG; g++) gptr[g] = n;
}

// ---------------- fused GAT aggregation (warp per destination node) ----------------
__global__ void gat_aggregate(const int* __restrict__ ptr, const int* __restrict__ csr,
                              const float* __restrict__ asrc, const float* __restrict__ adst,
                              const float* __restrict__ xw, const float* __restrict__ bias,
                              uint32_t* __restrict__ hs, int n_rows) {
    int row = blockIdx.x * 8 + (threadIdx.x >> 5);
    int lane = threadIdx.x & 31;
    if (row >= n_rows) return;
    int start = ptr[row], end = ptr[row + 1];
    float ad = adst[row];

    float m = -INFINITY;
    for (int e = start + lane; e < end; e += 32) {
        float a = asrc[csr[e]] + ad;
        a = a > 0.f ? a : 0.01f * a;
        m = fmaxf(m, a);
    }
    m = warp_max_all(m);

    float4 acc = make_float4(0.f, 0.f, 0.f, 0.f);
    float sum = 0.f;
    for (int base = start; base < end; base += 32) {
        int e = base + lane;
        float w = 0.f;
        int s = 0;
        if (e < end) {
            s = csr[e];
            float a = asrc[s] + ad;
            a = a > 0.f ? a : 0.01f * a;
            w = expf(a - m);
            sum += w;
        }
        int cnt = min(32, end - base);
        for (int j = 0; j < cnt; j++) {
            float wj = __shfl_sync(FULL, w, j);
            int sj = __shfl_sync(FULL, s, j);
            float4 v = ((const float4*)(xw + (size_t)sj * HH))[lane];
            acc.x += wj * v.x;
            acc.y += wj * v.y;
            acc.z += wj * v.z;
            acc.w += wj * v.w;
        }
    }
    sum = warp_sum_all(sum);
    float rinv = 1.f / (sum + 1e-16f);
    float4 b4 = ((const float4*)bias)[lane];
    float o0 = acc.x * rinv + b4.x;
    float o1 = acc.y * rinv + b4.y;
    float o2 = acc.z * rinv + b4.z;
    float o3 = acc.w * rinv + b4.w;
    o0 = o0 > 0.f ? o0 : expf(o0) - 1.f;
    o1 = o1 > 0.f ? o1 : expf(o1) - 1.f;
    o2 = o2 > 0.f ? o2 : expf(o2) - 1.f;
    o3 = o3 > 0.f ? o3 : expf(o3) - 1.f;
    uint32_t hp0, lp0, hp1, lp1;
    split_pair(o0, o1, hp0, lp0);
    split_pair(o2, o3, hp1, lp1);
    uint32_t* hr = hs + (size_t)row * 256;
    int w0 = ilv(2 * lane), w1 = ilv(2 * lane + 1);
    hr[w0] = hp0;
    hr[w0 + 2] = lp0;
    hr[w1] = hp1;
    hr[w1 + 2] = lp1;
}

// ---------------- GRU combine (rz-concat form) ----------------
__global__ void gru_combine2(const float* __restrict__ grz, const float* __restrict__ gih,
                             const float* __restrict__ hprev, float* __restrict__ outp,
                             uint32_t* __restrict__ outs, int rows) {
    int idx = blockIdx.x * blockDim.x + threadIdx.x;
    if (idx >= rows * 64) return;
    int r = idx >> 6, cp = idx & 63;
    float2 vr = *(const float2*)(grz + (size_t)r * 256 + 2 * cp);
    float2 vz = *(const float2*)(grz + (size_t)r * 256 + 128 + 2 * cp);
    float2 vin = *(const float2*)(gih + (size_t)r * 256 + 2 * cp);
    float2 vhn = *(const float2*)(gih + (size_t)r * 256 + 128 + 2 * cp);
    float2 hp2 = *(const float2*)(hprev + (size_t)r * HH + 2 * cp);
    float o[2];
    {
        float rr = 1.f / (1.f + expf(-vr.x));
        float z = 1.f / (1.f + expf(-vz.x));
        float n = tanhf(vin.x + rr * vhn.x);
        float v = (1.f - z) * n + z * hp2.x;
        o[0] = v > 0.f ? v : 0.f;
    }
    {
        float rr = 1.f / (1.f + expf(-vr.y));
        float z = 1.f / (1.f + expf(-vz.y));
        float n = tanhf(vin.y + rr * vhn.y);
        float v = (1.f - z) * n + z * hp2.y;
        o[1] = v > 0.f ? v : 0.f;
    }
    ((float2*)(outp + (size_t)r * HH))[cp] = make_float2(o[0], o[1]);
    uint32_t hp, lp;
    split_pair(o[0], o[1], hp, lp);
    int w = 128 + ilv(cp);
    outs[(size_t)r * 256 + w] = hp;
    outs[(size_t)r * 256 + w + 2] = lp;
}

// ---------------- molecule readout (warp per graph) ----------------
__global__ void graph_sum(const float* __restrict__ xc, const int* __restrict__ gptr,
                          float* __restrict__ outG, uint32_t* __restrict__ outGs, int n_g) {
    int g = blockIdx.x * 8 + (threadIdx.x >> 5);
    int lane = threadIdx.x & 31;
    if (g >= n_g) return;
    int start = gptr[g], end = gptr[g + 1];
    float4 acc = make_float4(0.f, 0.f, 0.f, 0.f);
    for (int i = start; i < end; i++) {
        float4 v = ((const float4*)(xc + (size_t)i * HH))[lane];
        acc.x += v.x; acc.y += v.y; acc.z += v.z; acc.w += v.w;
    }
    acc.x = fmaxf(acc.x, 0.f);
    acc.y = fmaxf(acc.y, 0.f);
    acc.z = fmaxf(acc.z, 0.f);
    acc.w = fmaxf(acc.w, 0.f);
    ((float4*)(outG + (size_t)g * HH))[lane] = acc;
    uint32_t hp0, lp0, hp1, lp1;
    split_pair(acc.x, acc.y, hp0, lp0);
    split_pair(acc.z, acc.w, hp1, lp1);
    uint32_t* orow = outGs + (size_t)g * 256;
    int w0 = 128 + ilv(2 * lane), w1 = 128 + ilv(2 * lane + 1);
    orow[w0] = hp0;
    orow[w0 + 2] = lp0;
    orow[w1] = hp1;
    orow[w1 + 2] = lp1;
}

__global__ void compute_vvec(const float* __restrict__ molW, const float* __restrict__ attdst,
                             float* __restrict__ v) {
    int k = threadIdx.x;
    float s = 0.f;
    for (int j = 0; j < HH; j++) s += molW[(size_t)j * HH + k] * attdst[j];
    v[k] = s;
}

__global__ void mol_timestep(const float* __restrict__ outG, const float* __restrict__ vvec,
                             const int* __restrict__ gptr, const float* __restrict__ asrc,
                             const float* __restrict__ xw, const float* __restrict__ bias,
                             uint32_t* __restrict__ hGs, int n_g) {
    int g = blockIdx.x * 8 + (threadIdx.x >> 5);
    int lane = threadIdx.x & 31;
    if (g >= n_g) return;
    float4 ov = ((const float4*)(outG + (size_t)g * HH))[lane];
    float4 vv = ((const float4*)vvec)[lane];
    float ad = warp_sum_all(ov.x * vv.x + ov.y * vv.y + ov.z * vv.z + ov.w * vv.w);

    int start = gptr[g], end = gptr[g + 1];
    float m = -INFINITY;
    for (int i = start + lane; i < end; i += 32) {
        float a = asrc[i] + ad;
        a = a > 0.f ? a : 0.01f * a;
        m = fmaxf(m, a);
    }
    m = warp_max_all(m);

    float4 acc = make_float4(0.f, 0.f, 0.f, 0.f);
    float sum = 0.f;
    for (int base = start; base < end; base += 32) {
        int i = base + lane;
        float w = 0.f;
        if (i < end) {
            float a = asrc[i] + ad;
            a = a > 0.f ? a : 0.01f * a;
            w = expf(a - m);
            sum += w;
        }
        int cnt = min(32, end - base);
        for (int j = 0; j < cnt; j++) {
            float wj = __shfl_sync(FULL, w, j);
            float4 v = ((const float4*)(xw + (size_t)(base + j) * HH))[lane];
            acc.x += wj * v.x;
            acc.y += wj * v.y;
            acc.z += wj * v.z;
            acc.w += wj * v.w;
        }
    }
    sum = warp_sum_all(sum);
    float rinv = 1.f / (sum + 1e-16f);
    float4 b4 = ((const float4*)bias)[lane];
    float o0 = acc.x * rinv + b4.x;
    float o1 = acc.y * rinv + b4.y;
    float o2 = acc.z * rinv + b4.z;
    float o3 = acc.w * rinv + b4.w;
    o0 = o0 > 0.f ? o0 : expf(o0) - 1.f;
    o1 = o1 > 0.f ? o1 : expf(o1) - 1.f;
    o2 = o2 > 0.f ? o2 : expf(o2) - 1.f;
    o3 = o3 > 0.f ? o3 : expf(o3) - 1.f;
    uint32_t hp0, lp0, hp1, lp1;
    split_pair(o0, o1, hp0, lp0);
    split_pair(o2, o3, hp1, lp1);
    uint32_t* hrow = hGs + (size_t)g * 256;
    int w0 = ilv(2 * lane), w1 = ilv(2 * lane + 1);
    hrow[w0] = hp0;
    hrow[w0 + 2] = lp0;
    hrow[w1] = hp1;
    hrow[w1 + 2] = lp1;
}

__global__ void final_out(const float* __restrict__ outG, const float* __restrict__ W,
                          const float* __restrict__ b, float* __restrict__ y, int g_rows) {
    int g = (blockIdx.x * blockDim.x + threadIdx.x) >> 5;
    int lane = threadIdx.x & 31;
    if (g >= g_rows) return;
    float4 v = ((const float4*)(outG + (size_t)g * HH))[lane];
    const float* vp = &v.x;
    float s = 0.f;
#pragma unroll
    for (int j = 0; j < 4; j++) s += vp[j] * W[lane * 4 + j];
    s = warp_sum_all(s);
    if (lane == 0) y[g] = s + b[0];
}

// ---------------- host ----------------
static inline int cdiv(int a, int b) { return (a + b - 1) / b; }

static inline GJob mkjob(const uint32_t* B, const float* bias, float* C, uint32_t* Cs,
                         int aoff, int K, int ldc, int coff, int csld, int csoff, int act) {
    GJob j;
    j.B = B; j.bias = bias; j.C = C; j.Cs = Cs;
    j.av = nullptr; j.aout = nullptr; j.av2 = nullptr; j.aout2 = nullptr;
    j.ab = nullptr; j.abstride = 0; j.aact = 0;
    j.aoff = aoff; j.K = K; j.ldc = ldc; j.coff = coff;
    j.csld = csld; j.csoff = csoff; j.act = act;
    return j;
}

extern "C" void kernel_launch(void* const* d_in, const int* in_sizes, int n_in,
                              void* d_out, int out_size) {
    const float* x = (const float*)d_in[0];
    const int* ei = (const int*)d_in[1];
    const int* batch = (const int*)d_in[2];
    const float* lin1_W = (const float*)d_in[3];
    const float* lin1_b = (const float*)d_in[4];
    const float* gate_W1 = (const float*)d_in[5];
    const float* gate_W2 = (const float*)d_in[6];
    const float* gate_att_l = (const float*)d_in[7];
    const float* gate_att_r = (const float*)d_in[8];
    const float* gate_bias = (const float*)d_in[9];
    const float* gru0_Wi = (const float*)d_in[10];
    const float* gru0_bi = (const float*)d_in[11];
    const float* gru0_Wh = (const float*)d_in[12];
    const float* gru0_bh = (const float*)d_in[13];
    const float* atom_W = (const float*)d_in[14];
    const float* atom_att_src = (const float*)d_in[15];
    const float* atom_att_dst = (const float*)d_in[16];
    const float* atom_bias = (const float*)d_in[17];
    const float* atom_gru_Wi = (const float*)d_in[18];
    const float* atom_gru_bi = (const float*)d_in[19];
    const float* atom_gru_Wh = (const float*)d_in[20];
    const float* atom_gru_bh = (const float*)d_in[21];
    const float* mol_W = (const float*)d_in[22];
    const float* mol_att_src = (const float*)d_in[23];
    const float* mol_att_dst = (const float*)d_in[24];
    const float* mol_bias = (const float*)d_in[25];
    const float* mol_gru_Wi = (const float*)d_in[26];
    const float* mol_gru_bi = (const float*)d_in[27];
    const float* mol_gru_Wh = (const float*)d_in[28];
    const float* mol_gru_bh = (const float*)d_in[29];
    const float* lin2_W = (const float*)d_in[30];
    const float* lin2_b = (const float*)d_in[31];

    const int* src = ei;
    const int* dst = ei + EE;

    cudaFuncSetAttribute(bgemm, cudaFuncAttributeMaxDynamicSharedMemorySize, BG_SMEM);

    float *x0, *xw, *xc, *grz, *gih, *asrc, *adst, *outG, *grzG, *gihG, *vvec;
    int *deg, *ptr, *cur, *csr_src, *bsum, *gptr;
    uint32_t *sx, *shx, *shxG;
    uint32_t *wl1, *wg1, *wg2, *watom, *wmol;
    uint32_t *wrz0, *wrza, *wrzm, *win0, *whn0, *wina, *whna, *winm, *whnm;
    float *brz0, *brza, *brzm;
    cudaGetSymbolAddress((void**)&x0, d_x0);
    cudaGetSymbolAddress((void**)&xw, d_xw);
    cudaGetSymbolAddress((void**)&xc, d_xc);
    cudaGetSymbolAddress((void**)&grz, d_gi);
    cudaGetSymbolAddress((void**)&gih, d_gh);
    cudaGetSymbolAddress((void**)&asrc, d_asrc);
    cudaGetSymbolAddress((void**)&adst, d_adst);
    cudaGetSymbolAddress((void**)&outG, d_outG);
    cudaGetSymbolAddress((void**)&grzG, d_giG);
    cudaGetSymbolAddress((void**)&gihG, d_ghG);
    cudaGetSymbolAddress((void**)&vvec, d_vvec);
    cudaGetSymbolAddress((void**)&deg, d_deg);
    cudaGetSymbolAddress((void**)&ptr, d_ptr);
    cudaGetSymbolAddress((void**)&cur, d_cur);
    cudaGetSymbolAddress((void**)&csr_src, d_csr_src);
    cudaGetSymbolAddress((void**)&bsum, d_bsum);
    cudaGetSymbolAddress((void**)&gptr, d_gptr);
    cudaGetSymbolAddress((void**)&sx, s_x);
    cudaGetSymbolAddress((void**)&shx, s_hx);
    cudaGetSymbolAddress((void**)&shxG, s_hxG);
    cudaGetSymbolAddress((void**)&wl1, w_lin1);
    cudaGetSymbolAddress((void**)&wg1, w_g1);
    cudaGetSymbolAddress((void**)&wg2, w_g2);
    cudaGetSymbolAddress((void**)&watom, w_atom);
    cudaGetSymbolAddress((void**)&wmol, w_mol);
    cudaGetSymbolAddress((void**)&wrz0, w_rz0);
    cudaGetSymbolAddress((void**)&wrza, w_rza);
    cudaGetSymbolAddress((void**)&wrzm, w_rzm);
    cudaGetSymbolAddress((void**)&win0, w_in0);
    cudaGetSymbolAddress((void**)&whn0, w_hn0);
    cudaGetSymbolAddress((void**)&wina, w_ina);
    cudaGetSymbolAddress((void**)&whna, w_hna);
    cudaGetSymbolAddress((void**)&winm, w_inm);
    cudaGetSymbolAddress((void**)&whnm, w_hnm);
    cudaGetSymbolAddress((void**)&brz0, b_rz0);
    cudaGetSymbolAddress((void**)&brza, b_rza);
    cudaGetSymbolAddress((void**)&brzm, b_rzm);

    int wpb_n = cdiv(NN, 8);
    int wpb_g = cdiv(GG, 8);
    const int nscan = cdiv(NN, 1024);
    const int rt_n = cdiv(NN, 128);
    const int rt_g = cdiv(GG, 128);

    // ---- batched weight prep ----
    SDescs sd;
    sd.d[0] = {lin1_W, wl1, IN_CH, HH, IN_CH};
    sd.d[1] = {gate_W1, wg1, HH + 1, HH, HH};
    sd.d[2] = {gate_W2, wg2, HH, HH, HH};
    sd.d[3] = {mol_W, wmol, HH, HH, HH};
    sd.d[4] = {atom_W, watom, HH, HH, HH};
    sd.d[5] = {atom_W + (size_t)HH * HH, watom + (size_t)HH * HH, HH, HH, HH};
    sd.d[6] = {gru0_Wi + 256 * HH, win0, HH, HH, HH};
    sd.d[7] = {gru0_Wh + 256 * HH, whn0, HH, HH, HH};
    sd.d[8] = {atom_gru_Wi + 256 * HH, wina, HH, HH, HH};
    sd.d[9] = {atom_gru_Wi + (size_t)H3 * HH + 256 * HH, wina + (size_t)HH * HH, HH, HH, HH};
    sd.d[10] = {atom_gru_Wh + 256 * HH, whna, HH, HH, HH};
    sd.d[11] = {atom_gru_Wh + (size_t)H3 * HH + 256 * HH, whna + (size_t)HH * HH, HH, HH, HH};
    sd.d[12] = {mol_gru_Wi + 256 * HH, winm, HH, HH, HH};
    sd.d[13] = {mol_gru_Wh + 256 * HH, whnm, HH, HH, HH};
    to_split_batch<<<dim3(14, 8), 256>>>(sd);

    CDescs cd;
    cd.d[0] = {gru0_Wi, gru0_Wh, wrz0, gru0_bi, gru0_bh, brz0};
    cd.d[1] = {atom_gru_Wi, atom_gru_Wh, wrza, atom_gru_bi, atom_gru_bh, brza};
    cd.d[2] = {atom_gru_Wi + (size_t)H3 * HH, atom_gru_Wh + (size_t)H3 * HH,
               wrza + 256 * 256, atom_gru_bi + H3, atom_gru_bh + H3, brza + 256};
    cd.d[3] = {mol_gru_Wi, mol_gru_Wh, wrzm, mol_gru_bi, mol_gru_bh, brzm};
    concat_rz_batch<<<dim3(4, 16), 256>>>(cd);

    to_split_x<<<cdiv(NN * 32, 256), 256>>>(x, sx);

    // ---- CSR + graph-pointer build ----
    cudaMemsetAsync(deg, 0, NN * sizeof(int));
    hist_kernel<<<cdiv(EE, 256), 256>>>(dst, deg, EE);
    scan_block<<<nscan, 256>>>(deg, ptr, bsum, NN);
    scan_bsum<<<1, 128>>>(bsum, nscan);
    scan_fixup<<<cdiv(NN, 256), 256>>>(ptr, bsum, cur, NN, EE);
    scatter_csr<<<cdiv(EE, 256), 256>>>(src, dst, cur, csr_src, EE);
    build_gptr<<<cdiv(NN, 256), 256>>>(batch, gptr, NN);

    GLaunch L;

    // x0 = lrelu(x @ lin1_W^T + b): fp32 + split + fused adst = x0 . att_r (plain store)
    L.j[0] = mkjob(wl1, lin1_b, x0, shx, 0, IN_CH, HH, 0, 256, 128, 1);
    L.j[0].av = gate_att_r; L.j[0].aout = adst;
    L.jid[0] = 0; L.ctile[0] = 0;
    bgemm<<<dim3(1, rt_n), 128, BG_SMEM>>>(L, sx, IN_CH, NN);

    // ---- GATEConv: wg1 dot-only (asrc) + wg2 (-> xw) ----
    L.j[0] = mkjob(wg1, nullptr, nullptr, nullptr, 128, HH, 0, 0, 0, 0, 0);
    L.j[0].av = gate_att_l; L.j[0].aout = asrc;
    L.j[0].ab = gate_W1 + HH; L.j[0].abstride = HH + 1; L.j[0].aact = 1;
    L.j[1] = mkjob(wg2, nullptr, xw, nullptr, 128, HH, HH, 0, 0, 0, 0);
    L.jid[0] = 0; L.ctile[0] = 0;
    L.jid[1] = 1; L.ctile[1] = 0;
    bgemm<<<dim3(2, rt_n), 128, BG_SMEM>>>(L, shx, 256, NN);
    gat_aggregate<<<wpb_n, 256>>>(ptr, csr_src, asrc, adst, xw, gate_bias, shx, NN);
    // merged GRU gemms: rz (2 tiles) + in + hn
    L.j[0] = mkjob(wrz0, brz0, grz, nullptr, 0, 256, 256, 0, 0, 0, 0);
    L.j[1] = mkjob(win0, gru0_bi + 256, gih, nullptr, 0, HH, 256, 0, 0, 0, 0);
    L.j[2] = mkjob(whn0, gru0_bh + 256, gih, nullptr, 128, HH, 256, 128, 0, 0, 0);
    L.jid[0] = 0; L.ctile[0] = 0;
    L.jid[1] = 0; L.ctile[1] = 1;
    L.jid[2] = 1; L.ctile[2] = 0;
    L.jid[3] = 2; L.ctile[3] = 0;
    bgemm<<<dim3(4, rt_n), 128, BG_SMEM>>>(L, shx, 256, NN);
    gru_combine2<<<cdiv(NN * 64, 256), 256>>>(grz, gih, x0, xc, shx, NN);

    // ---- extra atom GAT + GRU layers ----
    for (int l = 0; l < 2; l++) {
        L.j[0] = mkjob(watom + (size_t)l * HH * HH, nullptr, xw, nullptr, 128, HH, HH, 0, 0, 0, 0);
        L.j[0].av = atom_att_src + l * HH; L.j[0].aout = asrc;
        L.j[0].av2 = atom_att_dst + l * HH; L.j[0].aout2 = adst;
        L.jid[0] = 0; L.ctile[0] = 0;
        bgemm<<<dim3(1, rt_n), 128, BG_SMEM>>>(L, shx, 256, NN);
        gat_aggregate<<<wpb_n, 256>>>(ptr, csr_src, asrc, adst, xw, atom_bias + l * HH, shx, NN);
        L.j[0] = mkjob(wrza + (size_t)l * 256 * 256, brza + l * 256, grz, nullptr, 0, 256, 256, 0, 0, 0, 0);
        L.j[1] = mkjob(wina + (size_t)l * HH * HH, atom_gru_bi + l * H3 + 256, gih, nullptr, 0, HH, 256, 0, 0, 0, 0);
        L.j[2] = mkjob(whna + (size_t)l * HH * HH, atom_gru_bh + l * H3 + 256, gih, nullptr, 128, HH, 256, 128, 0, 0, 0);
        L.jid[0] = 0; L.ctile[0] = 0;
        L.jid[1] = 0; L.ctile[1] = 1;
        L.jid[2] = 1; L.ctile[2] = 0;
        L.jid[3] = 2; L.ctile[3] = 0;
        bgemm<<<dim3(4, rt_n), 128, BG_SMEM>>>(L, shx, 256, NN);
        gru_combine2<<<cdiv(NN * 64, 256), 256>>>(grz, gih, xc, xc, shx, NN);
    }

    // ---- molecule readout ----
    graph_sum<<<wpb_g, 256>>>(xc, gptr, outG, shxG, GG);
    L.j[0] = mkjob(wmol, nullptr, xw, nullptr, 128, HH, HH, 0, 0, 0, 0);
    L.j[0].av = mol_att_src; L.j[0].aout = asrc;
    L.jid[0] = 0; L.ctile[0] = 0;
    bgemm<<<dim3(1, rt_n), 128, BG_SMEM>>>(L, shx, 256, NN);
    compute_vvec<<<1, HH>>>(mol_W, mol_att_dst, vvec);

    for (int t = 0; t < 2; t++) {
        mol_timestep<<<wpb_g, 256>>>(outG, vvec, gptr, asrc, xw, mol_bias, shxG, GG);
        L.j[0] = mkjob(wrzm, brzm, grzG, nullptr, 0, 256, 256, 0, 0, 0, 0);
        L.j[1] = mkjob(winm, mol_gru_bi + 256, gihG, nullptr, 0, HH, 256, 0, 0, 0, 0);
        L.j[2] = mkjob(whnm, mol_gru_bh + 256, gihG, nullptr, 128, HH, 256, 128, 0, 0, 0);
        L.jid[0] = 0; L.ctile[0] = 0;
        L.jid[1] = 0; L.ctile[1] = 1;
        L.jid[2] = 1; L.ctile[2] = 0;
        L.jid[3] = 2; L.ctile[3] = 0;
        bgemm<<<dim3(4, rt_g), 128, BG_SMEM>>>(L, shxG, 256, GG);
        gru_combine2<<<cdiv(GG * 64, 256), 256>>>(grzG, gihG, outG, outG, shxG, GG);
    }

    final_out<<<wpb_g, 256>>>(outG, lin2_W, lin2_b, (float*)d_out, GG);
}

// round 15
// speedup vs baseline: 1.0185x; 1.0185x over previous
#include <cuda_runtime.h>
#include <cuda_bf16.h>
#include <math.h>
#include <stdint.h>

#define NN 100000
#define EE 1600000
#define IN_CH 64
#define HH 128
#define H3 384
#define GG 4096
#define FULL 0xffffffffu
#define BG_SMEM 49152   // 3 stages x 4096 words

// ---------------- scratch (no allocations allowed) ----------------
__device__ float d_x0[NN * HH];
__device__ float d_xw[NN * HH];
__device__ float d_xc[NN * HH];
__device__ float d_gi[NN * H3];     // grz (NN x 256)
__device__ float d_gh[NN * H3];     // gih (NN x 256)
__device__ float d_asrc[NN];
__device__ float d_adst[NN];
__device__ float d_outG[GG * HH];
__device__ float d_giG[GG * H3];
__device__ float d_ghG[GG * H3];
__device__ float d_vvec[HH];
__device__ int d_deg[NN];
__device__ int d_ptr[NN + 1];
__device__ int d_cur[NN];
__device__ int d_csr_src[EE];
__device__ int d_bsum[128];
__device__ int d_gptr[GG + 1];
// combined split activation buffers: row = 256 words = [h split | x split]
__device__ uint32_t s_hx[NN * 256];
__device__ uint32_t s_hxG[GG * 256];
__device__ uint32_t s_x[NN * IN_CH];
// split weights
__device__ uint32_t w_lin1[HH * IN_CH];
__device__ uint32_t w_g1[HH * HH];
__device__ uint32_t w_g2[HH * HH];
__device__ uint32_t w_atom[2 * HH * HH];
__device__ uint32_t w_mol[HH * HH];
__device__ uint32_t w_rz0[256 * 256];
__device__ uint32_t w_rza[2 * 256 * 256];
__device__ uint32_t w_rzm[256 * 256];
__device__ uint32_t w_in0[HH * HH];
__device__ uint32_t w_hn0[HH * HH];
__device__ uint32_t w_ina[2 * HH * HH];
__device__ uint32_t w_hna[2 * HH * HH];
__device__ uint32_t w_inm[HH * HH];
__device__ uint32_t w_hnm[HH * HH];
__device__ float b_rz0[256];
__device__ float b_rza[2 * 256];
__device__ float b_rzm[256];

// ---------------- helpers ----------------
__device__ __forceinline__ float warp_sum_all(float v) {
#pragma unroll
    for (int o = 16; o > 0; o >>= 1) v += __shfl_xor_sync(FULL, v, o);
    return v;
}

__device__ __forceinline__ int ilv(int cp) {
    int c = cp >> 3, p = cp & 7;
    return (c << 4) + ((p < 4) ? (p << 2) : (((p - 4) << 2) + 1));
}

__device__ __forceinline__ void split_pair(float f0, float f1, uint32_t& hp, uint32_t& lp) {
    uint32_t u0 = __float_as_uint(f0), u1 = __float_as_uint(f1);
    hp = __byte_perm(u0, u1, 0x7632);
    float l0 = f0 - __uint_as_float(u0 & 0xffff0000u);
    float l1 = f1 - __uint_as_float(u1 & 0xffff0000u);
    __nv_bfloat162 p = __floats2bfloat162_rn(l0, l1);
    lp = *reinterpret_cast<uint32_t*>(&p);
}

__device__ __forceinline__ void mma_bf16(float* c, const uint32_t* a, const uint32_t* b) {
    asm volatile(
        "mma.sync.aligned.m16n8k16.row.col.f32.bf16.bf16.f32 "
        "{%0,%1,%2,%3}, {%4,%5,%6,%7}, {%8,%9}, {%0,%1,%2,%3};"
        : "+f"(c[0]), "+f"(c[1]), "+f"(c[2]), "+f"(c[3])
        : "r"(a[0]), "r"(a[1]), "r"(a[2]), "r"(a[3]), "r"(b[0]), "r"(b[1]));
}

__device__ __forceinline__ void cp_async16(uint32_t dst, const void* src, bool pred) {
    asm volatile("cp.async.cg.shared.global [%0], [%1], 16, %2;"
                 :: "r"(dst), "l"(src), "r"(pred ? 16 : 0));
}

// ---------------- batched weight split ----------------
struct SDesc { const float* src; uint32_t* dst; int ld, M, K; };
struct SDescs { SDesc d[14]; };

__global__ void to_split_batch(SDescs ds) {
    SDesc d = ds.d[blockIdx.x];
    int kh = d.K >> 1;
    int total = d.M * kh;
    for (int idx = blockIdx.y * 256 + threadIdx.x; idx < total; idx += gridDim.y * 256) {
        int r = idx / kh, j = idx - r * kh;
        float f0 = d.src[(size_t)r * d.ld + 2 * j];
        float f1 = d.src[(size_t)r * d.ld + 2 * j + 1];
        uint32_t hp, lp;
        split_pair(f0, f1, hp, lp);
        int w = ilv(j);
        d.dst[(size_t)r * d.K + w] = hp;
        d.dst[(size_t)r * d.K + w + 2] = lp;
    }
}

struct CDesc { const float* wi; const float* wh; uint32_t* dst; const float* bi; const float* bh; float* brz; };
struct CDescs { CDesc d[4]; };

__global__ void concat_rz_batch(CDescs ds) {
    CDesc d = ds.d[blockIdx.x];
    for (int idx = blockIdx.y * 256 + threadIdx.x; idx < 256 * 128; idx += gridDim.y * 256) {
        int n = idx >> 7, j = idx & 127;
        float f0, f1;
        if (j < 64) {
            f0 = d.wi[(size_t)n * HH + 2 * j];
            f1 = d.wi[(size_t)n * HH + 2 * j + 1];
        } else {
            f0 = d.wh[(size_t)n * HH + 2 * (j - 64)];
            f1 = d.wh[(size_t)n * HH + 2 * (j - 64) + 1];
        }
        uint32_t hp, lp;
        split_pair(f0, f1, hp, lp);
        int w = ilv(j);
        d.dst[(size_t)n * 256 + w] = hp;
        d.dst[(size_t)n * 256 + w + 2] = lp;
        if (j == 0) d.brz[n] = d.bi[n] + d.bh[n];
    }
}

__global__ void to_split_x(const float* __restrict__ src, uint32_t* __restrict__ dst) {
    int idx = blockIdx.x * blockDim.x + threadIdx.x;
    if (idx >= NN * 32) return;
    int r = idx >> 5, j = idx & 31;
    float f0 = src[(size_t)r * IN_CH + 2 * j];
    float f1 = src[(size_t)r * IN_CH + 2 * j + 1];
    uint32_t hp, lp;
    split_pair(f0, f1, hp, lp);
    int w = ilv(j);
    dst[(size_t)r * IN_CH + w] = hp;
    dst[(size_t)r * IN_CH + w + 2] = lp;
}

// ---------------- bf16-split tensor-core GEMM: multi-job, depth-3 pipeline ----------------
struct GJob {
    const uint32_t* B;
    const float* bias;
    float* C;
    uint32_t* Cs;
    int aoff, K, ldc, coff, csld, csoff, act;
};
struct GLaunch {
    GJob j[3];
    int jid[4];
    int ctile[4];
};

__device__ __forceinline__ void bload(const uint32_t* __restrict__ Ahl, int lda, int aoff,
                                      const uint32_t* __restrict__ Bhl, int K,
                                      int M, int row0, int col0,
                                      int tid, int kc, uint32_t* sb) {
#pragma unroll
    for (int it = 0; it < 8; it++) {
        int s = tid * 8 + it;
        int r = (s >> 2) & 127;
        int j = s & 3;
        bool isB = s >= 512;
        uint32_t da = (uint32_t)__cvta_generic_to_shared(sb + (isB ? 2048 : 0) + r * 16 + 4 * j);
        const uint32_t* g;
        bool pred = true;
        if (!isB) {
            int ar = row0 + r;
            pred = ar < M;
            g = Ahl + (size_t)(pred ? ar : 0) * lda + aoff + kc * 16 + 4 * j;
        } else {
            g = Bhl + (size_t)(col0 + r) * K + kc * 16 + 4 * j;
        }
        cp_async16(da, g, pred);
    }
    asm volatile("cp.async.commit_group;");
}

__global__ void __launch_bounds__(128) bgemm(GLaunch L, const uint32_t* __restrict__ Ahl,
                                             int lda, int M) {
    extern __shared__ uint32_t sm[];
    const GJob J = L.j[L.jid[blockIdx.x]];
    const int col0 = L.ctile[blockIdx.x] * 128;
    const int tid = threadIdx.x;
    const int lane = tid & 31;
    const int warp = tid >> 5;
    const int g = lane >> 2;
    const int t = lane & 3;
    const int wrow = (warp >> 1) * 64;
    const int wcol = (warp & 1) * 64;
    const int row0 = blockIdx.y * 128;
    const int nk = J.K >> 4;

    float acc[4][8][4];
#pragma unroll
    for (int mt = 0; mt < 4; mt++)
#pragma unroll
        for (int nt = 0; nt < 8; nt++)
#pragma unroll
            for (int i = 0; i < 4; i++) acc[mt][nt][i] = 0.f;

    bload(Ahl, lda, J.aoff, J.B, J.K, M, row0, col0, tid, 0, sm);
    bload(Ahl, lda, J.aoff, J.B, J.K, M, row0, col0, tid, 1, sm + 4096);

    for (int c = 0; c < nk; c++) {
        if (c + 1 < nk)
            asm volatile("cp.async.wait_group 1;");
        else
            asm volatile("cp.async.wait_group 0;");
        __syncthreads();
        if (c + 2 < nk) {
            int nb = c + 2; nb -= (nb / 3) * 3;
            bload(Ahl, lda, J.aoff, J.B, J.K, M, row0, col0, tid, c + 2, sm + nb * 4096);
        }
        int cb = c; cb -= (cb / 3) * 3;
        const uint32_t* As = sm + cb * 4096;
        const uint32_t* Bs = As + 2048;

        uint32_t bhi[8][2], blo[8][2];
#pragma unroll
        for (int nt = 0; nt < 8; nt++) {
            int cc = wcol + nt * 8 + g;
            uint4 bb = *(const uint4*)(Bs + cc * 16 + 4 * t);
            bhi[nt][0] = bb.x; bhi[nt][1] = bb.y;
            blo[nt][0] = bb.z; blo[nt][1] = bb.w;
        }
#pragma unroll
        for (int mt = 0; mt < 4; mt++) {
            int r = wrow + mt * 16 + g;
            uint4 a0 = *(const uint4*)(As + r * 16 + 4 * t);
            uint4 a8 = *(const uint4*)(As + (r + 8) * 16 + 4 * t);
            uint32_t ahi[4] = {a0.x, a8.x, a0.y, a8.y};
            uint32_t alo[4] = {a0.z, a8.z, a0.w, a8.w};
#pragma unroll
            for (int nt = 0; nt < 8; nt++) {
                mma_bf16(acc[mt][nt], alo, bhi[nt]);
                mma_bf16(acc[mt][nt], ahi, blo[nt]);
                mma_bf16(acc[mt][nt], ahi, bhi[nt]);
            }
        }
    }

#pragma unroll
    for (int mt = 0; mt < 4; mt++) {
#pragma unroll
        for (int nt = 0; nt < 8; nt++) {
            int r0 = row0 + wrow + mt * 16 + g;
            int cl = wcol + nt * 8 + 2 * t;
            int cg = col0 + cl;
            float b0 = J.bias ? J.bias[cg] : 0.f;
            float b1 = J.bias ? J.bias[cg + 1] : 0.f;
            float v00 = acc[mt][nt][0] + b0, v01 = acc[mt][nt][1] + b1;
            float v10 = acc[mt][nt][2] + b0, v11 = acc[mt][nt][3] + b1;
            if (J.act == 1) {
                v00 = v00 > 0.f ? v00 : 0.01f * v00;
                v01 = v01 > 0.f ? v01 : 0.01f * v01;
                v10 = v10 > 0.f ? v10 : 0.01f * v10;
                v11 = v11 > 0.f ? v11 : 0.01f * v11;
            }
            if (r0 < M) {
                J.C[(size_t)r0 * J.ldc + J.coff + cg] = v00;
                J.C[(size_t)r0 * J.ldc + J.coff + cg + 1] = v01;
                if (J.Cs) {
                    uint32_t hp, lp;
                    split_pair(v00, v01, hp, lp);
                    int w = J.csoff + ilv(cl >> 1);
                    J.Cs[(size_t)r0 * J.csld + w] = hp;
                    J.Cs[(size_t)r0 * J.csld + w + 2] = lp;
                }
            }
            if (r0 + 8 < M) {
                J.C[(size_t)(r0 + 8) * J.ldc + J.coff + cg] = v10;
                J.C[(size_t)(r0 + 8) * J.ldc + J.coff + cg + 1] = v11;
                if (J.Cs) {
                    uint32_t hp, lp;
                    split_pair(v10, v11, hp, lp);
                    int w = J.csoff + ilv(cl >> 1);
                    J.Cs[(size_t)(r0 + 8) * J.csld + w] = hp;
                    J.Cs[(size_t)(r0 + 8) * J.csld + w + 2] = lp;
                }
            }
        }
    }
}

// ---------------- CSR build ----------------
__global__ void hist_kernel(const int* __restrict__ dst, int* __restrict__ deg, int n_e) {
    int e = blockIdx.x * blockDim.x + threadIdx.x;
    if (e < n_e) atomicAdd(&deg[dst[e]], 1);
}

__global__ void scan_block(const int* __restrict__ in, int* __restrict__ out,
                           int* __restrict__ bsum, int n) {
    __shared__ int s[256];
    int t = threadIdx.x;
    int base = blockIdx.x * 1024 + t * 4;
    int v[4];
#pragma unroll
    for (int j = 0; j < 4; j++) v[j] = (base + j < n) ? in[base + j] : 0;
    int tsum = v[0] + v[1] + v[2] + v[3];
    s[t] = tsum;
    __syncthreads();
    for (int off = 1; off < 256; off <<= 1) {
        int x = (t >= off) ? s[t - off] : 0;
        __syncthreads();
        s[t] += x;
        __syncthreads();
    }
    int exc = s[t] - tsum;
    if (t == 255) bsum[blockIdx.x] = s[t];
    int run = exc;
#pragma unroll
    for (int j = 0; j < 4; j++) {
        if (base + j < n) out[base + j] = run;
        run += v[j];
    }
}

__global__ void scan_bsum(int* __restrict__ bsum, int nb) {
    __shared__ int s[128];
    int t = threadIdx.x;
    int orig = (t < nb) ? bsum[t] : 0;
    s[t] = orig;
    __syncthreads();
    for (int off = 1; off < 128; off <<= 1) {
        int x = (t >= off) ? s[t - off] : 0;
        __syncthreads();
        s[t] += x;
        __syncthreads();
    }
    if (t < nb) bsum[t] = s[t] - orig;
}

__global__ void scan_fixup(int* __restrict__ ptr, const int* __restrict__ bsum,
                           int* __restrict__ cur, int n, int total) {
    int i = blockIdx.x * blockDim.x + threadIdx.x;
    if (i < n) {
        int p = ptr[i] + bsum[i >> 10];
        ptr[i] = p;
        cur[i] = p;
    }
    if (i == 0) ptr[n] = total;
}

__global__ void scatter_csr(const int* __restrict__ src, const int* __restrict__ dst,
                            int* __restrict__ cur, int* __restrict__ csr_src, int n_e) {
    int e = blockIdx.x * blockDim.x + threadIdx.x;
    if (e >= n_e) return;
    int p = atomicAdd(&cur[dst[e]], 1);
    csr_src[p] = src[e];
}

__global__ void build_gptr(const int* __restrict__ batch, int* __restrict__ gptr, int n) {
    int i = blockIdx.x * blockDim.x + threadIdx.x;
    if (i >= n) return;
    int b = batch[i];
    int prev = (i == 0) ? -1 : batch[i - 1];
    for (int g = prev + 1; g <= b; g++) gptr[g] = i;
    if (i == n - 1)
        for (int g = b + 1; g <= GG; g++) gptr[g] = n;
}

// ---------------- fused GAT aggregation (warp per destination node) ----------------
// single pass: softmax without max-shift (logits are O(1) here; shift-invariant)
__global__ void gat_aggregate(const int* __restrict__ ptr, const int* __restrict__ csr,
                              const float* __restrict__ asrc, const float* __restrict__ adst,
                              const float* __restrict__ xw, const float* __restrict__ bias,
                              uint32_t* __restrict__ hs, int n_rows) {
    int row = blockIdx.x * 8 + (threadIdx.x >> 5);
    int lane = threadIdx.x & 31;
    if (row >= n_rows) return;
    int start = ptr[row], end = ptr[row + 1];
    float ad = adst[row];

    float4 acc = make_float4(0.f, 0.f, 0.f, 0.f);
    float sum = 0.f;
    for (int base = start; base < end; base += 32) {
        int e = base + lane;
        float w = 0.f;
        int s = 0;
        if (e < end) {
            s = csr[e];
            float a = asrc[s] + ad;
            a = a > 0.f ? a : 0.01f * a;
            w = expf(a);
            sum += w;
        }
        int cnt = min(32, end - base);
        for (int j = 0; j < cnt; j++) {
            float wj = __shfl_sync(FULL, w, j);
            int sj = __shfl_sync(FULL, s, j);
            float4 v = ((const float4*)(xw + (size_t)sj * HH))[lane];
            acc.x += wj * v.x;
            acc.y += wj * v.y;
            acc.z += wj * v.z;
            acc.w += wj * v.w;
        }
    }
    sum = warp_sum_all(sum);
    float rinv = 1.f / (sum + 1e-16f);
    float4 b4 = ((const float4*)bias)[lane];
    float o0 = acc.x * rinv + b4.x;
    float o1 = acc.y * rinv + b4.y;
    float o2 = acc.z * rinv + b4.z;
    float o3 = acc.w * rinv + b4.w;
    o0 = o0 > 0.f ? o0 : expf(o0) - 1.f;
    o1 = o1 > 0.f ? o1 : expf(o1) - 1.f;
    o2 = o2 > 0.f ? o2 : expf(o2) - 1.f;
    o3 = o3 > 0.f ? o3 : expf(o3) - 1.f;
    uint32_t hp0, lp0, hp1, lp1;
    split_pair(o0, o1, hp0, lp0);
    split_pair(o2, o3, hp1, lp1);
    uint32_t* hr = hs + (size_t)row * 256;
    int w0 = ilv(2 * lane), w1 = ilv(2 * lane + 1);
    hr[w0] = hp0;
    hr[w0 + 2] = lp0;
    hr[w1] = hp1;
    hr[w1 + 2] = lp1;
}

// ---------------- GATEConv per-node attention scalars ----------------
__global__ void gate_node_atts(const float* __restrict__ tmp, const float* __restrict__ W1,
                               const float* __restrict__ att_l, const float* __restrict__ x0,
                               const float* __restrict__ att_r, float* __restrict__ asrc,
                               float* __restrict__ adst, int n_rows) {
    int w = (blockIdx.x * blockDim.x + threadIdx.x) >> 5;
    int lane = threadIdx.x & 31;
    if (w >= n_rows) return;
    float4 tv = ((const float4*)(tmp + (size_t)w * HH))[lane];
    float4 xv = ((const float4*)(x0 + (size_t)w * HH))[lane];
    float s1 = 0.f, s2 = 0.f;
    const float* t = &tv.x;
    const float* xp = &xv.x;
#pragma unroll
    for (int j = 0; j < 4; j++) {
        int k = lane * 4 + j;
        float xe = t[j] + W1[(size_t)k * (HH + 1) + HH];
        xe = xe > 0.f ? xe : 0.01f * xe;
        s1 += xe * att_l[k];
        s2 += xp[j] * att_r[k];
    }
    s1 = warp_sum_all(s1);
    s2 = warp_sum_all(s2);
    if (lane == 0) { asrc[w] = s1; adst[w] = s2; }
}

__global__ void node_two_dots(const float* __restrict__ xw, const float* __restrict__ v1,
                              const float* __restrict__ v2, float* __restrict__ o1,
                              float* __restrict__ o2, int n_rows) {
    int w = (blockIdx.x * blockDim.x + threadIdx.x) >> 5;
    int lane = threadIdx.x & 31;
    if (w >= n_rows) return;
    float4 xv = ((const float4*)(xw + (size_t)w * HH))[lane];
    const float* xp = &xv.x;
    float s1 = 0.f, s2 = 0.f;
#pragma unroll
    for (int j = 0; j < 4; j++) {
        int k = lane * 4 + j;
        s1 += xp[j] * v1[k];
        s2 += xp[j] * v2[k];
    }
    s1 = warp_sum_all(s1);
    s2 = warp_sum_all(s2);
    if (lane == 0) { o1[w] = s1; o2[w] = s2; }
}

__global__ void node_one_dot(const float* __restrict__ xw, const float* __restrict__ v1,
                             float* __restrict__ o1, int n_rows) {
    int w = (blockIdx.x * blockDim.x + threadIdx.x) >> 5;
    int lane = threadIdx.x & 31;
    if (w >= n_rows) return;
    float4 xv = ((const float4*)(xw + (size_t)w * HH))[lane];
    const float* xp = &xv.x;
    float s1 = 0.f;
#pragma unroll
    for (int j = 0; j < 4; j++) s1 += xp[j] * v1[lane * 4 + j];
    s1 = warp_sum_all(s1);
    if (lane == 0) o1[w] = s1;
}

// ---------------- GRU combine (rz-concat form) ----------------
__global__ void gru_combine2(const float* __restrict__ grz, const float* __restrict__ gih,
                             const float* __restrict__ hprev, float* __restrict__ outp,
                             uint32_t* __restrict__ outs, int rows) {
    int idx = blockIdx.x * blockDim.x + threadIdx.x;
    if (idx >= rows * 64) return;
    int r = idx >> 6, cp = idx & 63;
    float2 vr = *(const float2*)(grz + (size_t)r * 256 + 2 * cp);
    float2 vz = *(const float2*)(grz + (size_t)r * 256 + 128 + 2 * cp);
    float2 vin = *(const float2*)(gih + (size_t)r * 256 + 2 * cp);
    float2 vhn = *(const float2*)(gih + (size_t)r * 256 + 128 + 2 * cp);
    float2 hp2 = *(const float2*)(hprev + (size_t)r * HH + 2 * cp);
    float o[2];
    {
        float rr = 1.f / (1.f + expf(-vr.x));
        float z = 1.f / (1.f + expf(-vz.x));
        float n = tanhf(vin.x + rr * vhn.x);
        float v = (1.f - z) * n + z * hp2.x;
        o[0] = v > 0.f ? v : 0.f;
    }
    {
        float rr = 1.f / (1.f + expf(-vr.y));
        float z = 1.f / (1.f + expf(-vz.y));
        float n = tanhf(vin.y + rr * vhn.y);
        float v = (1.f - z) * n + z * hp2.y;
        o[1] = v > 0.f ? v : 0.f;
    }
    ((float2*)(outp + (size_t)r * HH))[cp] = make_float2(o[0], o[1]);
    uint32_t hp, lp;
    split_pair(o[0], o[1], hp, lp);
    int w = 128 + ilv(cp);
    outs[(size_t)r * 256 + w] = hp;
    outs[(size_t)r * 256 + w + 2] = lp;
}

// ---------------- molecule readout (warp per graph) ----------------
__global__ void graph_sum(const float* __restrict__ xc, const int* __restrict__ gptr,
                          float* __restrict__ outG, uint32_t* __restrict__ outGs, int n_g) {
    int g = blockIdx.x * 8 + (threadIdx.x >> 5);
    int lane = threadIdx.x & 31;
    if (g >= n_g) return;
    int start = gptr[g], end = gptr[g + 1];
    float4 acc = make_float4(0.f, 0.f, 0.f, 0.f);
    for (int i = start; i < end; i++) {
        float4 v = ((const float4*)(xc + (size_t)i * HH))[lane];
        acc.x += v.x; acc.y += v.y; acc.z += v.z; acc.w += v.w;
    }
    acc.x = fmaxf(acc.x, 0.f);
    acc.y = fmaxf(acc.y, 0.f);
    acc.z = fmaxf(acc.z, 0.f);
    acc.w = fmaxf(acc.w, 0.f);
    ((float4*)(outG + (size_t)g * HH))[lane] = acc;
    uint32_t hp0, lp0, hp1, lp1;
    split_pair(acc.x, acc.y, hp0, lp0);
    split_pair(acc.z, acc.w, hp1, lp1);
    uint32_t* orow = outGs + (size_t)g * 256;
    int w0 = 128 + ilv(2 * lane), w1 = 128 + ilv(2 * lane + 1);
    orow[w0] = hp0;
    orow[w0 + 2] = lp0;
    orow[w1] = hp1;
    orow[w1 + 2] = lp1;
}

__global__ void compute_vvec(const float* __restrict__ molW, const float* __restrict__ attdst,
                             float* __restrict__ v) {
    int k = threadIdx.x;
    float s = 0.f;
    for (int j = 0; j < HH; j++) s += molW[(size_t)j * HH + k] * attdst[j];
    v[k] = s;
}

// single pass: softmax without max-shift
__global__ void mol_timestep(const float* __restrict__ outG, const float* __restrict__ vvec,
                             const int* __restrict__ gptr, const float* __restrict__ asrc,
                             const float* __restrict__ xw, const float* __restrict__ bias,
                             uint32_t* __restrict__ hGs, int n_g) {
    int g = blockIdx.x * 8 + (threadIdx.x >> 5);
    int lane = threadIdx.x & 31;
    if (g >= n_g) return;
    float4 ov = ((const float4*)(outG + (size_t)g * HH))[lane];
    float4 vv = ((const float4*)vvec)[lane];
    float ad = warp_sum_all(ov.x * vv.x + ov.y * vv.y + ov.z * vv.z + ov.w * vv.w);

    int start = gptr[g], end = gptr[g + 1];
    float4 acc = make_float4(0.f, 0.f, 0.f, 0.f);
    float sum = 0.f;
    for (int base = start; base < end; base += 32) {
        int i = base + lane;
        float w = 0.f;
        if (i < end) {
            float a = asrc[i] + ad;
            a = a > 0.f ? a : 0.01f * a;
            w = expf(a);
            sum += w;
        }
        int cnt = min(32, end - base);
        for (int j = 0; j < cnt; j++) {
            float wj = __shfl_sync(FULL, w, j);
            float4 v = ((const float4*)(xw + (size_t)(base + j) * HH))[lane];
            acc.x += wj * v.x;
            acc.y += wj * v.y;
            acc.z += wj * v.z;
            acc.w += wj * v.w;
        }
    }
    sum = warp_sum_all(sum);
    float rinv = 1.f / (sum + 1e-16f);
    float4 b4 = ((const float4*)bias)[lane];
    float o0 = acc.x * rinv + b4.x;
    float o1 = acc.y * rinv + b4.y;
    float o2 = acc.z * rinv + b4.z;
    float o3 = acc.w * rinv + b4.w;
    o0 = o0 > 0.f ? o0 : expf(o0) - 1.f;
    o1 = o1 > 0.f ? o1 : expf(o1) - 1.f;
    o2 = o2 > 0.f ? o2 : expf(o2) - 1.f;
    o3 = o3 > 0.f ? o3 : expf(o3) - 1.f;
    uint32_t hp0, lp0, hp1, lp1;
    split_pair(o0, o1, hp0, lp0);
    split_pair(o2, o3, hp1, lp1);
    uint32_t* hrow = hGs + (size_t)g * 256;
    int w0 = ilv(2 * lane), w1 = ilv(2 * lane + 1);
    hrow[w0] = hp0;
    hrow[w0 + 2] = lp0;
    hrow[w1] = hp1;
    hrow[w1 + 2] = lp1;
}

__global__ void final_out(const float* __restrict__ outG, const float* __restrict__ W,
                          const float* __restrict__ b, float* __restrict__ y, int g_rows) {
    int g = (blockIdx.x * blockDim.x + threadIdx.x) >> 5;
    int lane = threadIdx.x & 31;
    if (g >= g_rows) return;
    float4 v = ((const float4*)(outG + (size_t)g * HH))[lane];
    const float* vp = &v.x;
    float s = 0.f;
#pragma unroll
    for (int j = 0; j < 4; j++) s += vp[j] * W[lane * 4 + j];
    s = warp_sum_all(s);
    if (lane == 0) y[g] = s + b[0];
}

// ---------------- host ----------------
static inline int cdiv(int a, int b) { return (a + b - 1) / b; }

static inline GJob mkjob(const uint32_t* B, const float* bias, float* C, uint32_t* Cs,
                         int aoff, int K, int ldc, int coff, int csld, int csoff, int act) {
    GJob j;
    j.B = B; j.bias = bias; j.C = C; j.Cs = Cs;
    j.aoff = aoff; j.K = K; j.ldc = ldc; j.coff = coff;
    j.csld = csld; j.csoff = csoff; j.act = act;
    return j;
}

extern "C" void kernel_launch(void* const* d_in, const int* in_sizes, int n_in,
                              void* d_out, int out_size) {
    const float* x = (const float*)d_in[0];
    const int* ei = (const int*)d_in[1];
    const int* batch = (const int*)d_in[2];
    const float* lin1_W = (const float*)d_in[3];
    const float* lin1_b = (const float*)d_in[4];
    const float* gate_W1 = (const float*)d_in[5];
    const float* gate_W2 = (const float*)d_in[6];
    const float* gate_att_l = (const float*)d_in[7];
    const float* gate_att_r = (const float*)d_in[8];
    const float* gate_bias = (const float*)d_in[9];
    const float* gru0_Wi = (const float*)d_in[10];
    const float* gru0_bi = (const float*)d_in[11];
    const float* gru0_Wh = (const float*)d_in[12];
    const float* gru0_bh = (const float*)d_in[13];
    const float* atom_W = (const float*)d_in[14];
    const float* atom_att_src = (const float*)d_in[15];
    const float* atom_att_dst = (const float*)d_in[16];
    const float* atom_bias = (const float*)d_in[17];
    const float* atom_gru_Wi = (const float*)d_in[18];
    const float* atom_gru_bi = (const float*)d_in[19];
    const float* atom_gru_Wh = (const float*)d_in[20];
    const float* atom_gru_bh = (const float*)d_in[21];
    const float* mol_W = (const float*)d_in[22];
    const float* mol_att_src = (const float*)d_in[23];
    const float* mol_att_dst = (const float*)d_in[24];
    const float* mol_bias = (const float*)d_in[25];
    const float* mol_gru_Wi = (const float*)d_in[26];
    const float* mol_gru_bi = (const float*)d_in[27];
    const float* mol_gru_Wh = (const float*)d_in[28];
    const float* mol_gru_bh = (const float*)d_in[29];
    const float* lin2_W = (const float*)d_in[30];
    const float* lin2_b = (const float*)d_in[31];

    const int* src = ei;
    const int* dst = ei + EE;

    cudaFuncSetAttribute(bgemm, cudaFuncAttributeMaxDynamicSharedMemorySize, BG_SMEM);

    float *x0, *xw, *xc, *grz, *gih, *asrc, *adst, *outG, *grzG, *gihG, *vvec;
    int *deg, *ptr, *cur, *csr_src, *bsum, *gptr;
    uint32_t *sx, *shx, *shxG;
    uint32_t *wl1, *wg1, *wg2, *watom, *wmol;
    uint32_t *wrz0, *wrza, *wrzm, *win0, *whn0, *wina, *whna, *winm, *whnm;
    float *brz0, *brza, *brzm;
    cudaGetSymbolAddress((void**)&x0, d_x0);
    cudaGetSymbolAddress((void**)&xw, d_xw);
    cudaGetSymbolAddress((void**)&xc, d_xc);
    cudaGetSymbolAddress((void**)&grz, d_gi);
    cudaGetSymbolAddress((void**)&gih, d_gh);
    cudaGetSymbolAddress((void**)&asrc, d_asrc);
    cudaGetSymbolAddress((void**)&adst, d_adst);
    cudaGetSymbolAddress((void**)&outG, d_outG);
    cudaGetSymbolAddress((void**)&grzG, d_giG);
    cudaGetSymbolAddress((void**)&gihG, d_ghG);
    cudaGetSymbolAddress((void**)&vvec, d_vvec);
    cudaGetSymbolAddress((void**)&deg, d_deg);
    cudaGetSymbolAddress((void**)&ptr, d_ptr);
    cudaGetSymbolAddress((void**)&cur, d_cur);
    cudaGetSymbolAddress((void**)&csr_src, d_csr_src);
    cudaGetSymbolAddress((void**)&bsum, d_bsum);
    cudaGetSymbolAddress((void**)&gptr, d_gptr);
    cudaGetSymbolAddress((void**)&sx, s_x);
    cudaGetSymbolAddress((void**)&shx, s_hx);
    cudaGetSymbolAddress((void**)&shxG, s_hxG);
    cudaGetSymbolAddress((void**)&wl1, w_lin1);
    cudaGetSymbolAddress((void**)&wg1, w_g1);
    cudaGetSymbolAddress((void**)&wg2, w_g2);
    cudaGetSymbolAddress((void**)&watom, w_atom);
    cudaGetSymbolAddress((void**)&wmol, w_mol);
    cudaGetSymbolAddress((void**)&wrz0, w_rz0);
    cudaGetSymbolAddress((void**)&wrza, w_rza);
    cudaGetSymbolAddress((void**)&wrzm, w_rzm);
    cudaGetSymbolAddress((void**)&win0, w_in0);
    cudaGetSymbolAddress((void**)&whn0, w_hn0);
    cudaGetSymbolAddress((void**)&wina, w_ina);
    cudaGetSymbolAddress((void**)&whna, w_hna);
    cudaGetSymbolAddress((void**)&winm, w_inm);
    cudaGetSymbolAddress((void**)&whnm, w_hnm);
    cudaGetSymbolAddress((void**)&brz0, b_rz0);
    cudaGetSymbolAddress((void**)&brza, b_rza);
    cudaGetSymbolAddress((void**)&brzm, b_rzm);

    int wpb_n = cdiv(NN, 8);
    int wpb_g = cdiv(GG, 8);
    const int nscan = cdiv(NN, 1024);
    const int rt_n = cdiv(NN, 128);
    const int rt_g = cdiv(GG, 128);

    // ---- batched weight prep ----
    SDescs sd;
    sd.d[0] = {lin1_W, wl1, IN_CH, HH, IN_CH};
    sd.d[1] = {gate_W1, wg1, HH + 1, HH, HH};
    sd.d[2] = {gate_W2, wg2, HH, HH, HH};
    sd.d[3] = {mol_W, wmol, HH, HH, HH};
    sd.d[4] = {atom_W, watom, HH, HH, HH};
    sd.d[5] = {atom_W + (size_t)HH * HH, watom + (size_t)HH * HH, HH, HH, HH};
    sd.d[6] = {gru0_Wi + 256 * HH, win0, HH, HH, HH};
    sd.d[7] = {gru0_Wh + 256 * HH, whn0, HH, HH, HH};
    sd.d[8] = {atom_gru_Wi + 256 * HH, wina, HH, HH, HH};
    sd.d[9] = {atom_gru_Wi + (size_t)H3 * HH + 256 * HH, wina + (size_t)HH * HH, HH, HH, HH};
    sd.d[10] = {atom_gru_Wh + 256 * HH, whna, HH, HH, HH};
    sd.d[11] = {atom_gru_Wh + (size_t)H3 * HH + 256 * HH, whna + (size_t)HH * HH, HH, HH, HH};
    sd.d[12] = {mol_gru_Wi + 256 * HH, winm, HH, HH, HH};
    sd.d[13] = {mol_gru_Wh + 256 * HH, whnm, HH, HH, HH};
    to_split_batch<<<dim3(14, 8), 256>>>(sd);

    CDescs cd;
    cd.d[0] = {gru0_Wi, gru0_Wh, wrz0, gru0_bi, gru0_bh, brz0};
    cd.d[1] = {atom_gru_Wi, atom_gru_Wh, wrza, atom_gru_bi, atom_gru_bh, brza};
    cd.d[2] = {atom_gru_Wi + (size_t)H3 * HH, atom_gru_Wh + (size_t)H3 * HH,
               wrza + 256 * 256, atom_gru_bi + H3, atom_gru_bh + H3, brza + 256};
    cd.d[3] = {mol_gru_Wi, mol_gru_Wh, wrzm, mol_gru_bi, mol_gru_bh, brzm};
    concat_rz_batch<<<dim3(4, 16), 256>>>(cd);

    to_split_x<<<cdiv(NN * 32, 256), 256>>>(x, sx);

    // ---- CSR + graph-pointer build ----
    cudaMemsetAsync(deg, 0, NN * sizeof(int));
    hist_kernel<<<cdiv(EE, 256), 256>>>(dst, deg, EE);
    scan_block<<<nscan, 256>>>(deg, ptr, bsum, NN);
    scan_bsum<<<1, 128>>>(bsum, nscan);
    scan_fixup<<<cdiv(NN, 256), 256>>>(ptr, bsum, cur, NN, EE);
    scatter_csr<<<cdiv(EE, 256), 256>>>(src, dst, cur, csr_src, EE);
    build_gptr<<<cdiv(NN, 256), 256>>>(batch, gptr, NN);

    GLaunch L;

    // x0 = lrelu(x @ lin1_W^T + b): fp32 + split into s_hx x-part
    L.j[0] = mkjob(wl1, lin1_b, x0, shx, 0, IN_CH, HH, 0, 256, 128, 1);
    L.jid[0] = 0; L.ctile[0] = 0;
    bgemm<<<dim3(1, rt_n), 128, BG_SMEM>>>(L, sx, IN_CH, NN);

    // ---- GATEConv: merged wg1 (-> gih temp) + wg2 (-> xw) ----
    L.j[0] = mkjob(wg1, nullptr, gih, nullptr, 128, HH, HH, 0, 0, 0, 0);
    L.j[1] = mkjob(wg2, nullptr, xw, nullptr, 128, HH, HH, 0, 0, 0, 0);
    L.jid[0] = 0; L.ctile[0] = 0;
    L.jid[1] = 1; L.ctile[1] = 0;
    bgemm<<<dim3(2, rt_n), 128, BG_SMEM>>>(L, shx, 256, NN);
    gate_node_atts<<<wpb_n, 256>>>(gih, gate_W1, gate_att_l, x0, gate_att_r, asrc, adst, NN);
    gat_aggregate<<<wpb_n, 256>>>(ptr, csr_src, asrc, adst, xw, gate_bias, shx, NN);
    // merged GRU gemms: rz (2 tiles) + in + hn
    L.j[0] = mkjob(wrz0, brz0, grz, nullptr, 0, 256, 256, 0, 0, 0, 0);
    L.j[1] = mkjob(win0, gru0_bi + 256, gih, nullptr, 0, HH, 256, 0, 0, 0, 0);
    L.j[2] = mkjob(whn0, gru0_bh + 256, gih, nullptr, 128, HH, 256, 128, 0, 0, 0);
    L.jid[0] = 0; L.ctile[0] = 0;
    L.jid[1] = 0; L.ctile[1] = 1;
    L.jid[2] = 1; L.ctile[2] = 0;
    L.jid[3] = 2; L.ctile[3] = 0;
    bgemm<<<dim3(4, rt_n), 128, BG_SMEM>>>(L, shx, 256, NN);
    gru_combine2<<<cdiv(NN * 64, 256), 256>>>(grz, gih, x0, xc, shx, NN);

    // ---- extra atom GAT + GRU layers ----
    for (int l = 0; l < 2; l++) {
        L.j[0] = mkjob(watom + (size_t)l * HH * HH, nullptr, xw, nullptr, 128, HH, HH, 0, 0, 0, 0);
        L.jid[0] = 0; L.ctile[0] = 0;
        bgemm<<<dim3(1, rt_n), 128, BG_SMEM>>>(L, shx, 256, NN);
        node_two_dots<<<wpb_n, 256>>>(xw, atom_att_src + l * HH, atom_att_dst + l * HH, asrc, adst, NN);
        gat_aggregate<<<wpb_n, 256>>>(ptr, csr_src, asrc, adst, xw, atom_bias + l * HH, shx, NN);
        L.j[0] = mkjob(wrza + (size_t)l * 256 * 256, brza + l * 256, grz, nullptr, 0, 256, 256, 0, 0, 0, 0);
        L.j[1] = mkjob(wina + (size_t)l * HH * HH, atom_gru_bi + l * H3 + 256, gih, nullptr, 0, HH, 256, 0, 0, 0, 0);
        L.j[2] = mkjob(whna + (size_t)l * HH * HH, atom_gru_bh + l * H3 + 256, gih, nullptr, 128, HH, 256, 128, 0, 0, 0);
        L.jid[0] = 0; L.ctile[0] = 0;
        L.jid[1] = 0; L.ctile[1] = 1;
        L.jid[2] = 1; L.ctile[2] = 0;
        L.jid[3] = 2; L.ctile[3] = 0;
        bgemm<<<dim3(4, rt_n), 128, BG_SMEM>>>(L, shx, 256, NN);
        gru_combine2<<<cdiv(NN * 64, 256), 256>>>(grz, gih, xc, xc, shx, NN);
    }

    // ---- molecule readout ----
    graph_sum<<<wpb_g, 256>>>(xc, gptr, outG, shxG, GG);
    L.j[0] = mkjob(wmol, nullptr, xw, nullptr, 128, HH, HH, 0, 0, 0, 0);
    L.jid[0] = 0; L.ctile[0] = 0;
    bgemm<<<dim3(1, rt_n), 128, BG_SMEM>>>(L, shx, 256, NN);
    node_one_dot<<<wpb_n, 256>>>(xw, mol_att_src, asrc, NN);
    compute_vvec<<<1, HH>>>(mol_W, mol_att_dst, vvec);

    for (int t = 0; t < 2; t++) {
        mol_timestep<<<wpb_g, 256>>>(outG, vvec, gptr, asrc, xw, mol_bias, shxG, GG);
        L.j[0] = mkjob(wrzm, brzm, grzG, nullptr, 0, 256, 256, 0, 0, 0, 0);
        L.j[1] = mkjob(winm, mol_gru_bi + 256, gihG, nullptr, 0, HH, 256, 0, 0, 0, 0);
        L.j[2] = mkjob(whnm, mol_gru_bh + 256, gihG, nullptr, 128, HH, 256, 128, 0, 0, 0);
        L.jid[0] = 0; L.ctile[0] = 0;
        L.jid[1] = 0; L.ctile[1] = 1;
        L.jid[2] = 1; L.ctile[2] = 0;
        L.jid[3] = 2; L.ctile[3] = 0;
        bgemm<<<dim3(4, rt_g), 128, BG_SMEM>>>(L, shxG, 256, GG);
        gru_combine2<<<cdiv(GG * 64, 256), 256>>>(grzG, gihG, outG, outG, shxG, GG);
    }

    final_out<<<wpb_g, 256>>>(outG, lin2_W, lin2_b, (float*)d_out, GG);
}